// round 3
// baseline (speedup 1.0000x reference)
#include <cuda_runtime.h>

#define B_   4
#define C_   128
#define H_   64
#define W_   64
#define KS_  7
#define PAD_ 3
#define NC_  8      // channel chunks
#define CC_  16     // channels per chunk ( == O/GROUPS, so chunk == group )
#define HW_  (H_*W_)

#define CHUNK_STRIDE_ ((size_t)H_*W_*CC_)            // per (b,cc) plane
#define MAT_STRIDE_   ((size_t)B_*NC_*H_*W_*CC_)     // per q/k/v matrix

// Scratch for q,k,v in chunked pixel-major layout: [mat][b][cc][y][x][16]
__device__ __align__(16) float g_qkv[3ull * B_ * NC_ * H_ * W_ * CC_];

// ---------------- packed f32x2 helpers (double-rate fp32 FMA) ----------------
__device__ __forceinline__ unsigned long long pack2(float a, float b) {
    unsigned long long r;
    asm("mov.b64 %0, {%1, %2};" : "=l"(r) : "f"(a), "f"(b));
    return r;
}
__device__ __forceinline__ unsigned long long fma2(unsigned long long a,
                                                   unsigned long long b,
                                                   unsigned long long c) {
    unsigned long long d;
    asm("fma.rn.f32x2 %0, %1, %2, %3;" : "=l"(d) : "l"(a), "l"(b), "l"(c));
    return d;
}

// ---------------- Kernel 1: fused QKV projection (1x1 conv == SGEMM) ---------
// grid.x = B*H (one row of 64 pixels), grid.y = 3 (q/k/v), block = 256
// Each thread: 4 pixels x 8 output channels, accumulated as f32x2 pairs.
__global__ __launch_bounds__(256) void proj_kernel(
    const float* __restrict__ x, const float* __restrict__ wq,
    const float* __restrict__ wk, const float* __restrict__ wv)
{
    __shared__ float Xs[16][64];     // [cin_k][pixel]
    __shared__ float Ws[16][132];    // [cin_k][out], padded pitch vs conflicts

    const int row = blockIdx.x;
    const int b = row >> 6, h = row & 63;
    const int mat = blockIdx.y;
    const float* wm = (mat == 0) ? wq : (mat == 1 ? wk : wv);

    const int t = threadIdx.x;
    const int pxg  = t & 15;   // pixel group of 4
    const int outg = t >> 4;   // out-channel group of 8

    unsigned long long acc2[4][4];
#pragma unroll
    for (int i = 0; i < 4; i++)
#pragma unroll
        for (int j = 0; j < 4; j++) acc2[i][j] = 0ull;

    const float* xrow = x + ((size_t)b * C_ * H_ + h) * W_;

    for (int c0 = 0; c0 < C_; c0 += 16) {
        __syncthreads();
        // X tile: 16 cin x 64 px (coalesced rows)
        for (int i = t; i < 16 * 64; i += 256) {
            int kk = i >> 6, px = i & 63;
            Xs[kk][px] = xrow[(size_t)(c0 + kk) * HW_ + px];
        }
        // W tile: coalesced 64B reads per out row
        for (int i = t; i < 16 * 128; i += 256) {
            int o = i >> 4, kk = i & 15;
            Ws[kk][o] = wm[o * C_ + c0 + kk];
        }
        __syncthreads();
#pragma unroll
        for (int kk = 0; kk < 16; kk++) {
            float4 xv = *(const float4*)&Xs[kk][pxg * 4];
            ulonglong2 wA = *(const ulonglong2*)&Ws[kk][outg * 8];
            ulonglong2 wB = *(const ulonglong2*)&Ws[kk][outg * 8 + 4];
            float xs4[4] = {xv.x, xv.y, xv.z, xv.w};
#pragma unroll
            for (int i = 0; i < 4; i++) {
                unsigned long long xb = pack2(xs4[i], xs4[i]);
                acc2[i][0] = fma2(xb, wA.x, acc2[i][0]);
                acc2[i][1] = fma2(xb, wA.y, acc2[i][1]);
                acc2[i][2] = fma2(xb, wB.x, acc2[i][2]);
                acc2[i][3] = fma2(xb, wB.y, acc2[i][3]);
            }
        }
    }

    // out channels o = outg*8 + j  ->  chunk cc = outg>>1, in-chunk base = (outg&1)*8
    const int cc = outg >> 1;
    const int cbase = (outg & 1) * 8;
    float* ob = g_qkv + (size_t)mat * MAT_STRIDE_ +
                ((size_t)(b * NC_ + cc) * H_ + h) * W_ * CC_ + cbase;
#pragma unroll
    for (int i = 0; i < 4; i++) {
        int ww = pxg * 4 + i;
        ulonglong2* p = (ulonglong2*)(ob + (size_t)ww * CC_);
        p[0] = make_ulonglong2(acc2[i][0], acc2[i][1]);
        p[1] = make_ulonglong2(acc2[i][2], acc2[i][3]);
    }
}

// ---------------- Kernel 2: windowed attention -------------------------------
#define TW_ 16
#define TH_ 8
#define KW_ (TW_ + KS_ - 1)   // 22
#define KH_ (TH_ + KS_ - 1)   // 14

__device__ __forceinline__ void load_tile(float4 kt[4][KH_][KW_],
                                          const float* __restrict__ cbp,
                                          int y0, int x0, int t)
{
    for (int i = t; i < KH_ * KW_ * 4; i += 128) {
        int c4 = i & 3;
        int lin = i >> 2;
        int xx = lin % KW_;
        int yy = lin / KW_;
        int gy = y0 - PAD_ + yy, gx = x0 - PAD_ + xx;
        float4 v = make_float4(0.f, 0.f, 0.f, 0.f);
        if (gy >= 0 && gy < H_ && gx >= 0 && gx < W_)
            v = *(const float4*)(cbp + ((size_t)gy * W_ + gx) * CC_ + c4 * 4);
        kt[c4][yy][xx] = v;
    }
}

__global__ __launch_bounds__(128) void attn_kernel(
    const float* __restrict__ relx, const float* __restrict__ rely,
    float* __restrict__ out)
{
    __shared__ float4 kt[4][KH_][KW_];   // one 16-channel chunk, [c4][y][x]
    __shared__ float srel[112];          // rel_x (56) + rel_y (56)

    const int t = threadIdx.x;
    const int tx = t & 15, ty = t >> 4;
    const int b = blockIdx.z;
    const int x0 = blockIdx.x * TW_, y0 = blockIdx.y * TH_;
    const int px = x0 + tx, py = y0 + ty;

    if (t < 56)       srel[t] = relx[t];
    else if (t < 112) srel[t] = rely[t - 56];

    const float* qb = g_qkv;
    const float* kb = g_qkv + MAT_STRIDE_;
    const float* vb = g_qkv + 2 * MAT_STRIDE_;

    float logit[49];
#pragma unroll
    for (int i = 0; i < 49; i++) logit[i] = 0.f;
    float qxs[8], qys[8];
#pragma unroll
    for (int i = 0; i < 8; i++) { qxs[i] = 0.f; qys[i] = 0.f; }

    // ---- pass 1: logits = q . k over 8 chunks of 16 channels ----
    for (int cc = 0; cc < NC_; cc++) {
        __syncthreads();
        load_tile(kt, kb + (size_t)(b * NC_ + cc) * CHUNK_STRIDE_, y0, x0, t);
        __syncthreads();

        const float4* qp = (const float4*)(qb + (size_t)(b * NC_ + cc) * CHUNK_STRIDE_ +
                                           ((size_t)py * W_ + px) * CC_);
        float4 q0 = qp[0], q1 = qp[1], q2 = qp[2], q3 = qp[3];

        // bias accumulators: chunk == group; channels 0..7 -> rel_x, 8..15 -> rel_y
        qxs[0] += q0.x; qxs[1] += q0.y; qxs[2] += q0.z; qxs[3] += q0.w;
        qxs[4] += q1.x; qxs[5] += q1.y; qxs[6] += q1.z; qxs[7] += q1.w;
        qys[0] += q2.x; qys[1] += q2.y; qys[2] += q2.z; qys[3] += q2.w;
        qys[4] += q3.x; qys[5] += q3.y; qys[6] += q3.z; qys[7] += q3.w;

#pragma unroll
        for (int ki = 0; ki < KS_; ki++) {
#pragma unroll
            for (int kj = 0; kj < KS_; kj++) {
                float4 k0 = kt[0][ty + ki][tx + kj];
                float4 k1 = kt[1][ty + ki][tx + kj];
                float4 k2 = kt[2][ty + ki][tx + kj];
                float4 k3 = kt[3][ty + ki][tx + kj];
                float s = logit[ki * KS_ + kj];
                s = fmaf(q0.x, k0.x, s); s = fmaf(q0.y, k0.y, s);
                s = fmaf(q0.z, k0.z, s); s = fmaf(q0.w, k0.w, s);
                s = fmaf(q1.x, k1.x, s); s = fmaf(q1.y, k1.y, s);
                s = fmaf(q1.z, k1.z, s); s = fmaf(q1.w, k1.w, s);
                s = fmaf(q2.x, k2.x, s); s = fmaf(q2.y, k2.y, s);
                s = fmaf(q2.z, k2.z, s); s = fmaf(q2.w, k2.w, s);
                s = fmaf(q3.x, k3.x, s); s = fmaf(q3.y, k3.y, s);
                s = fmaf(q3.z, k3.z, s); s = fmaf(q3.w, k3.w, s);
                logit[ki * KS_ + kj] = s;
            }
        }
    }

    // ---- bias + softmax (fully thread-local over 49 taps) ----
    float bxv[7], byv[7];
#pragma unroll
    for (int kj = 0; kj < 7; kj++) {
        float s = 0.f;
#pragma unroll
        for (int xi = 0; xi < 8; xi++) s = fmaf(qxs[xi], srel[xi * 7 + kj], s);
        bxv[kj] = s;
    }
#pragma unroll
    for (int ki = 0; ki < 7; ki++) {
        float s = 0.f;
#pragma unroll
        for (int yi = 0; yi < 8; yi++) s = fmaf(qys[yi], srel[56 + yi * 7 + ki], s);
        byv[ki] = s;
    }
    float m = -1e30f;
#pragma unroll
    for (int ki = 0; ki < 7; ki++)
#pragma unroll
        for (int kj = 0; kj < 7; kj++) {
            float l = logit[ki * 7 + kj] + bxv[kj] + byv[ki];
            logit[ki * 7 + kj] = l;
            m = fmaxf(m, l);
        }
    float ssum = 0.f;
#pragma unroll
    for (int i = 0; i < 49; i++) {
        float e = __expf(logit[i] - m);
        logit[i] = e;
        ssum += e;
    }
    float inv = 1.f / ssum;
#pragma unroll
    for (int i = 0; i < 49; i++) logit[i] *= inv;

    // ---- pass 2: out = attn . v, chunk by chunk; write BCHW ----
    for (int cc = 0; cc < NC_; cc++) {
        __syncthreads();
        load_tile(kt, vb + (size_t)(b * NC_ + cc) * CHUNK_STRIDE_, y0, x0, t);
        __syncthreads();

        float4 o0 = make_float4(0.f,0.f,0.f,0.f), o1 = o0, o2 = o0, o3 = o0;
#pragma unroll
        for (int ki = 0; ki < KS_; ki++) {
#pragma unroll
            for (int kj = 0; kj < KS_; kj++) {
                float a = logit[ki * KS_ + kj];
                float4 v0 = kt[0][ty + ki][tx + kj];
                float4 v1 = kt[1][ty + ki][tx + kj];
                float4 v2 = kt[2][ty + ki][tx + kj];
                float4 v3 = kt[3][ty + ki][tx + kj];
                o0.x = fmaf(a, v0.x, o0.x); o0.y = fmaf(a, v0.y, o0.y);
                o0.z = fmaf(a, v0.z, o0.z); o0.w = fmaf(a, v0.w, o0.w);
                o1.x = fmaf(a, v1.x, o1.x); o1.y = fmaf(a, v1.y, o1.y);
                o1.z = fmaf(a, v1.z, o1.z); o1.w = fmaf(a, v1.w, o1.w);
                o2.x = fmaf(a, v2.x, o2.x); o2.y = fmaf(a, v2.y, o2.y);
                o2.z = fmaf(a, v2.z, o2.z); o2.w = fmaf(a, v2.w, o2.w);
                o3.x = fmaf(a, v3.x, o3.x); o3.y = fmaf(a, v3.y, o3.y);
                o3.z = fmaf(a, v3.z, o3.z); o3.w = fmaf(a, v3.w, o3.w);
            }
        }
        size_t ob = ((size_t)(b * C_ + cc * CC_) * H_ + py) * W_ + px;
        out[ob +  0*HW_] = o0.x; out[ob +  1*HW_] = o0.y;
        out[ob +  2*HW_] = o0.z; out[ob +  3*HW_] = o0.w;
        out[ob +  4*HW_] = o1.x; out[ob +  5*HW_] = o1.y;
        out[ob +  6*HW_] = o1.z; out[ob +  7*HW_] = o1.w;
        out[ob +  8*HW_] = o2.x; out[ob +  9*HW_] = o2.y;
        out[ob + 10*HW_] = o2.z; out[ob + 11*HW_] = o2.w;
        out[ob + 12*HW_] = o3.x; out[ob + 13*HW_] = o3.y;
        out[ob + 14*HW_] = o3.z; out[ob + 15*HW_] = o3.w;
    }
}

// ---------------- launch -----------------------------------------------------
extern "C" void kernel_launch(void* const* d_in, const int* in_sizes, int n_in,
                              void* d_out, int out_size)
{
    const float* x    = (const float*)d_in[0];
    const float* wq   = (const float*)d_in[1];
    const float* wk   = (const float*)d_in[2];
    const float* wv   = (const float*)d_in[3];
    const float* relx = (const float*)d_in[4];
    const float* rely = (const float*)d_in[5];
    float* out = (float*)d_out;

    proj_kernel<<<dim3(B_ * H_, 3), 256>>>(x, wq, wk, wv);
    attn_kernel<<<dim3(W_ / TW_, H_ / TH_, B_), 128>>>(relx, rely, out);
}

// round 4
// speedup vs baseline: 1.0186x; 1.0186x over previous
#include <cuda_runtime.h>

#define B_   4
#define C_   128
#define H_   64
#define W_   64
#define KS_  7
#define PAD_ 3
#define NC_  8      // channel chunks
#define CC_  16     // channels per chunk ( == O/GROUPS, so chunk == group )
#define HW_  (H_*W_)

#define CHUNK_STRIDE_ ((size_t)H_*W_*CC_)            // per (b,cc) plane
#define MAT_STRIDE_   ((size_t)B_*NC_*H_*W_*CC_)     // per q/k/v matrix

// Scratch for q,k,v in chunked pixel-major layout: [mat][b][cc][y][x][16]
__device__ __align__(16) float g_qkv[3ull * B_ * NC_ * H_ * W_ * CC_];

// ---------------- packed f32x2 helpers (double-rate fp32 FMA) ----------------
__device__ __forceinline__ unsigned long long pack2(float a, float b) {
    unsigned long long r;
    asm("mov.b64 %0, {%1, %2};" : "=l"(r) : "f"(a), "f"(b));
    return r;
}
__device__ __forceinline__ unsigned long long fma2(unsigned long long a,
                                                   unsigned long long b,
                                                   unsigned long long c) {
    unsigned long long d;
    asm("fma.rn.f32x2 %0, %1, %2, %3;" : "=l"(d) : "l"(a), "l"(b), "l"(c));
    return d;
}

// ---------------- Kernel 1: fused QKV projection (1x1 conv == SGEMM) ---------
// grid.x = B*H (one row of 64 pixels), grid.y = 3 (q/k/v), block = 256
// Each thread: 4 pixels x 8 output channels, accumulated as f32x2 pairs.
__global__ __launch_bounds__(256) void proj_kernel(
    const float* __restrict__ x, const float* __restrict__ wq,
    const float* __restrict__ wk, const float* __restrict__ wv)
{
    __shared__ float Xs[16][64];     // [cin_k][pixel]
    __shared__ float Ws[16][132];    // [cin_k][out], padded pitch vs conflicts

    const int row = blockIdx.x;
    const int b = row >> 6, h = row & 63;
    const int mat = blockIdx.y;
    const float* wm = (mat == 0) ? wq : (mat == 1 ? wk : wv);

    const int t = threadIdx.x;
    const int pxg  = t & 15;   // pixel group of 4
    const int outg = t >> 4;   // out-channel group of 8

    unsigned long long acc2[4][4];
#pragma unroll
    for (int i = 0; i < 4; i++)
#pragma unroll
        for (int j = 0; j < 4; j++) acc2[i][j] = 0ull;

    const float* xrow = x + ((size_t)b * C_ * H_ + h) * W_;

    for (int c0 = 0; c0 < C_; c0 += 16) {
        __syncthreads();
        // X tile: 16 cin x 64 px (coalesced rows)
        for (int i = t; i < 16 * 64; i += 256) {
            int kk = i >> 6, px = i & 63;
            Xs[kk][px] = xrow[(size_t)(c0 + kk) * HW_ + px];
        }
        // W tile: coalesced 64B reads per out row
        for (int i = t; i < 16 * 128; i += 256) {
            int o = i >> 4, kk = i & 15;
            Ws[kk][o] = wm[o * C_ + c0 + kk];
        }
        __syncthreads();
#pragma unroll
        for (int kk = 0; kk < 16; kk++) {
            float4 xv = *(const float4*)&Xs[kk][pxg * 4];
            ulonglong2 wA = *(const ulonglong2*)&Ws[kk][outg * 8];
            ulonglong2 wB = *(const ulonglong2*)&Ws[kk][outg * 8 + 4];
            float xs4[4] = {xv.x, xv.y, xv.z, xv.w};
#pragma unroll
            for (int i = 0; i < 4; i++) {
                unsigned long long xb = pack2(xs4[i], xs4[i]);
                acc2[i][0] = fma2(xb, wA.x, acc2[i][0]);
                acc2[i][1] = fma2(xb, wA.y, acc2[i][1]);
                acc2[i][2] = fma2(xb, wB.x, acc2[i][2]);
                acc2[i][3] = fma2(xb, wB.y, acc2[i][3]);
            }
        }
    }

    // out channels o = outg*8 + j  ->  chunk cc = outg>>1, in-chunk base = (outg&1)*8
    const int cc = outg >> 1;
    const int cbase = (outg & 1) * 8;
    float* ob = g_qkv + (size_t)mat * MAT_STRIDE_ +
                ((size_t)(b * NC_ + cc) * H_ + h) * W_ * CC_ + cbase;
#pragma unroll
    for (int i = 0; i < 4; i++) {
        int ww = pxg * 4 + i;
        ulonglong2* p = (ulonglong2*)(ob + (size_t)ww * CC_);
        p[0] = make_ulonglong2(acc2[i][0], acc2[i][1]);
        p[1] = make_ulonglong2(acc2[i][2], acc2[i][3]);
    }
}

// ---------------- Kernel 2: windowed attention -------------------------------
#define TW_ 16
#define TH_ 8
#define KW_ (TW_ + KS_ - 1)   // 22
#define KH_ (TH_ + KS_ - 1)   // 14

__device__ __forceinline__ void load_tile(float4 kt[4][KH_][KW_],
                                          const float* __restrict__ cbp,
                                          int y0, int x0, int t)
{
    for (int i = t; i < KH_ * KW_ * 4; i += 128) {
        int c4 = i & 3;
        int lin = i >> 2;
        int xx = lin % KW_;
        int yy = lin / KW_;
        int gy = y0 - PAD_ + yy, gx = x0 - PAD_ + xx;
        float4 v = make_float4(0.f, 0.f, 0.f, 0.f);
        if (gy >= 0 && gy < H_ && gx >= 0 && gx < W_)
            v = *(const float4*)(cbp + ((size_t)gy * W_ + gx) * CC_ + c4 * 4);
        kt[c4][yy][xx] = v;
    }
}

__global__ __launch_bounds__(128) void attn_kernel(
    const float* __restrict__ relx, const float* __restrict__ rely,
    float* __restrict__ out)
{
    __shared__ float4 kt[4][KH_][KW_];   // one 16-channel chunk, [c4][y][x]
    __shared__ float srel[112];          // rel_x (56) + rel_y (56)

    const int t = threadIdx.x;
    const int tx = t & 15, ty = t >> 4;
    const int b = blockIdx.z;
    const int x0 = blockIdx.x * TW_, y0 = blockIdx.y * TH_;
    const int px = x0 + tx, py = y0 + ty;

    if (t < 56)       srel[t] = relx[t];
    else if (t < 112) srel[t] = rely[t - 56];

    const float* qb = g_qkv;
    const float* kb = g_qkv + MAT_STRIDE_;
    const float* vb = g_qkv + 2 * MAT_STRIDE_;

    float logit[49];
#pragma unroll
    for (int i = 0; i < 49; i++) logit[i] = 0.f;
    float qxs[8], qys[8];
#pragma unroll
    for (int i = 0; i < 8; i++) { qxs[i] = 0.f; qys[i] = 0.f; }

    // ---- pass 1: logits = q . k over 8 chunks of 16 channels ----
    for (int cc = 0; cc < NC_; cc++) {
        __syncthreads();
        load_tile(kt, kb + (size_t)(b * NC_ + cc) * CHUNK_STRIDE_, y0, x0, t);
        __syncthreads();

        const float4* qp = (const float4*)(qb + (size_t)(b * NC_ + cc) * CHUNK_STRIDE_ +
                                           ((size_t)py * W_ + px) * CC_);
        float4 q0 = qp[0], q1 = qp[1], q2 = qp[2], q3 = qp[3];

        // bias accumulators: chunk == group; channels 0..7 -> rel_x, 8..15 -> rel_y
        qxs[0] += q0.x; qxs[1] += q0.y; qxs[2] += q0.z; qxs[3] += q0.w;
        qxs[4] += q1.x; qxs[5] += q1.y; qxs[6] += q1.z; qxs[7] += q1.w;
        qys[0] += q2.x; qys[1] += q2.y; qys[2] += q2.z; qys[3] += q2.w;
        qys[4] += q3.x; qys[5] += q3.y; qys[6] += q3.z; qys[7] += q3.w;

#pragma unroll
        for (int ki = 0; ki < KS_; ki++) {
#pragma unroll
            for (int kj = 0; kj < KS_; kj++) {
                float4 k0 = kt[0][ty + ki][tx + kj];
                float4 k1 = kt[1][ty + ki][tx + kj];
                float4 k2 = kt[2][ty + ki][tx + kj];
                float4 k3 = kt[3][ty + ki][tx + kj];
                float s = logit[ki * KS_ + kj];
                s = fmaf(q0.x, k0.x, s); s = fmaf(q0.y, k0.y, s);
                s = fmaf(q0.z, k0.z, s); s = fmaf(q0.w, k0.w, s);
                s = fmaf(q1.x, k1.x, s); s = fmaf(q1.y, k1.y, s);
                s = fmaf(q1.z, k1.z, s); s = fmaf(q1.w, k1.w, s);
                s = fmaf(q2.x, k2.x, s); s = fmaf(q2.y, k2.y, s);
                s = fmaf(q2.z, k2.z, s); s = fmaf(q2.w, k2.w, s);
                s = fmaf(q3.x, k3.x, s); s = fmaf(q3.y, k3.y, s);
                s = fmaf(q3.z, k3.z, s); s = fmaf(q3.w, k3.w, s);
                logit[ki * KS_ + kj] = s;
            }
        }
    }

    // ---- bias + softmax (fully thread-local over 49 taps) ----
    float bxv[7], byv[7];
#pragma unroll
    for (int kj = 0; kj < 7; kj++) {
        float s = 0.f;
#pragma unroll
        for (int xi = 0; xi < 8; xi++) s = fmaf(qxs[xi], srel[xi * 7 + kj], s);
        bxv[kj] = s;
    }
#pragma unroll
    for (int ki = 0; ki < 7; ki++) {
        float s = 0.f;
#pragma unroll
        for (int yi = 0; yi < 8; yi++) s = fmaf(qys[yi], srel[56 + yi * 7 + ki], s);
        byv[ki] = s;
    }
    float m = -1e30f;
#pragma unroll
    for (int ki = 0; ki < 7; ki++)
#pragma unroll
        for (int kj = 0; kj < 7; kj++) {
            float l = logit[ki * 7 + kj] + bxv[kj] + byv[ki];
            logit[ki * 7 + kj] = l;
            m = fmaxf(m, l);
        }
    float ssum = 0.f;
#pragma unroll
    for (int i = 0; i < 49; i++) {
        float e = __expf(logit[i] - m);
        logit[i] = e;
        ssum += e;
    }
    float inv = 1.f / ssum;
#pragma unroll
    for (int i = 0; i < 49; i++) logit[i] *= inv;

    // ---- pass 2: out = attn . v, chunk by chunk; write BCHW ----
    for (int cc = 0; cc < NC_; cc++) {
        __syncthreads();
        load_tile(kt, vb + (size_t)(b * NC_ + cc) * CHUNK_STRIDE_, y0, x0, t);
        __syncthreads();

        float4 o0 = make_float4(0.f,0.f,0.f,0.f), o1 = o0, o2 = o0, o3 = o0;
#pragma unroll
        for (int ki = 0; ki < KS_; ki++) {
#pragma unroll
            for (int kj = 0; kj < KS_; kj++) {
                float a = logit[ki * KS_ + kj];
                float4 v0 = kt[0][ty + ki][tx + kj];
                float4 v1 = kt[1][ty + ki][tx + kj];
                float4 v2 = kt[2][ty + ki][tx + kj];
                float4 v3 = kt[3][ty + ki][tx + kj];
                o0.x = fmaf(a, v0.x, o0.x); o0.y = fmaf(a, v0.y, o0.y);
                o0.z = fmaf(a, v0.z, o0.z); o0.w = fmaf(a, v0.w, o0.w);
                o1.x = fmaf(a, v1.x, o1.x); o1.y = fmaf(a, v1.y, o1.y);
                o1.z = fmaf(a, v1.z, o1.z); o1.w = fmaf(a, v1.w, o1.w);
                o2.x = fmaf(a, v2.x, o2.x); o2.y = fmaf(a, v2.y, o2.y);
                o2.z = fmaf(a, v2.z, o2.z); o2.w = fmaf(a, v2.w, o2.w);
                o3.x = fmaf(a, v3.x, o3.x); o3.y = fmaf(a, v3.y, o3.y);
                o3.z = fmaf(a, v3.z, o3.z); o3.w = fmaf(a, v3.w, o3.w);
            }
        }
        size_t ob = ((size_t)(b * C_ + cc * CC_) * H_ + py) * W_ + px;
        out[ob +  0*HW_] = o0.x; out[ob +  1*HW_] = o0.y;
        out[ob +  2*HW_] = o0.z; out[ob +  3*HW_] = o0.w;
        out[ob +  4*HW_] = o1.x; out[ob +  5*HW_] = o1.y;
        out[ob +  6*HW_] = o1.z; out[ob +  7*HW_] = o1.w;
        out[ob +  8*HW_] = o2.x; out[ob +  9*HW_] = o2.y;
        out[ob + 10*HW_] = o2.z; out[ob + 11*HW_] = o2.w;
        out[ob + 12*HW_] = o3.x; out[ob + 13*HW_] = o3.y;
        out[ob + 14*HW_] = o3.z; out[ob + 15*HW_] = o3.w;
    }
}

// ---------------- launch -----------------------------------------------------
extern "C" void kernel_launch(void* const* d_in, const int* in_sizes, int n_in,
                              void* d_out, int out_size)
{
    const float* x    = (const float*)d_in[0];
    const float* wq   = (const float*)d_in[1];
    const float* wk   = (const float*)d_in[2];
    const float* wv   = (const float*)d_in[3];
    const float* relx = (const float*)d_in[4];
    const float* rely = (const float*)d_in[5];
    float* out = (float*)d_out;

    proj_kernel<<<dim3(B_ * H_, 3), 256>>>(x, wq, wk, wv);
    attn_kernel<<<dim3(W_ / TW_, H_ / TH_, B_), 128>>>(relx, rely, out);
}

// round 5
// speedup vs baseline: 1.3138x; 1.2898x over previous
#include <cuda_runtime.h>

#define B_   4
#define C_   128
#define H_   64
#define W_   64
#define KS_  7
#define PAD_ 3
#define NC_  8      // channel chunks
#define CC_  16     // channels per chunk ( == O/GROUPS, so chunk == group )
#define HW_  (H_*W_)

#define CHUNK_STRIDE_ ((size_t)H_*W_*CC_)            // per (b,cc) plane
#define MAT_STRIDE_   ((size_t)B_*NC_*H_*W_*CC_)     // per q/k/v matrix

// Scratch for q,k,v in chunked pixel-major layout: [mat][b][cc][y][x][16]
__device__ __align__(16) float g_qkv[3ull * B_ * NC_ * H_ * W_ * CC_];

// ---------------- packed f32x2 helpers (double-rate fp32 FMA) ----------------
__device__ __forceinline__ unsigned long long pack2(float a, float b) {
    unsigned long long r;
    asm("mov.b64 %0, {%1, %2};" : "=l"(r) : "f"(a), "f"(b));
    return r;
}
__device__ __forceinline__ unsigned long long fma2(unsigned long long a,
                                                   unsigned long long b,
                                                   unsigned long long c) {
    unsigned long long d;
    asm("fma.rn.f32x2 %0, %1, %2, %3;" : "=l"(d) : "l"(a), "l"(b), "l"(c));
    return d;
}

// ---------------- Kernel 1: fused QKV projection (1x1 conv == SGEMM) ---------
__global__ __launch_bounds__(256) void proj_kernel(
    const float* __restrict__ x, const float* __restrict__ wq,
    const float* __restrict__ wk, const float* __restrict__ wv)
{
    __shared__ float Xs[16][64];     // [cin_k][pixel]
    __shared__ float Ws[16][132];    // [cin_k][out], padded pitch vs conflicts

    const int row = blockIdx.x;
    const int b = row >> 6, h = row & 63;
    const int mat = blockIdx.y;
    const float* wm = (mat == 0) ? wq : (mat == 1 ? wk : wv);

    const int t = threadIdx.x;
    const int pxg  = t & 15;   // pixel group of 4
    const int outg = t >> 4;   // out-channel group of 8

    unsigned long long acc2[4][4];
#pragma unroll
    for (int i = 0; i < 4; i++)
#pragma unroll
        for (int j = 0; j < 4; j++) acc2[i][j] = 0ull;

    const float* xrow = x + ((size_t)b * C_ * H_ + h) * W_;

    for (int c0 = 0; c0 < C_; c0 += 16) {
        __syncthreads();
        for (int i = t; i < 16 * 64; i += 256) {
            int kk = i >> 6, px = i & 63;
            Xs[kk][px] = xrow[(size_t)(c0 + kk) * HW_ + px];
        }
        for (int i = t; i < 16 * 128; i += 256) {
            int o = i >> 4, kk = i & 15;
            Ws[kk][o] = wm[o * C_ + c0 + kk];
        }
        __syncthreads();
#pragma unroll
        for (int kk = 0; kk < 16; kk++) {
            float4 xv = *(const float4*)&Xs[kk][pxg * 4];
            ulonglong2 wA = *(const ulonglong2*)&Ws[kk][outg * 8];
            ulonglong2 wB = *(const ulonglong2*)&Ws[kk][outg * 8 + 4];
            float xs4[4] = {xv.x, xv.y, xv.z, xv.w};
#pragma unroll
            for (int i = 0; i < 4; i++) {
                unsigned long long xb = pack2(xs4[i], xs4[i]);
                acc2[i][0] = fma2(xb, wA.x, acc2[i][0]);
                acc2[i][1] = fma2(xb, wA.y, acc2[i][1]);
                acc2[i][2] = fma2(xb, wB.x, acc2[i][2]);
                acc2[i][3] = fma2(xb, wB.y, acc2[i][3]);
            }
        }
    }

    const int cc = outg >> 1;
    const int cbase = (outg & 1) * 8;
    float* ob = g_qkv + (size_t)mat * MAT_STRIDE_ +
                ((size_t)(b * NC_ + cc) * H_ + h) * W_ * CC_ + cbase;
#pragma unroll
    for (int i = 0; i < 4; i++) {
        int ww = pxg * 4 + i;
        ulonglong2* p = (ulonglong2*)(ob + (size_t)ww * CC_);
        p[0] = make_ulonglong2(acc2[i][0], acc2[i][1]);
        p[1] = make_ulonglong2(acc2[i][2], acc2[i][3]);
    }
}

// ---------------- Kernel 2: windowed attention -------------------------------
#define TW_ 16
#define TH_ 8
#define KW_ (TW_ + KS_ - 1)        // 22
#define KH_ (TH_ + KS_ - 1)        // 14
#define NGR_ 4                      // warp-groups per block
#define PLANE_ (KH_ * KW_)          // 308
#define TILE_F4_ (4 * PLANE_)       // 1232 float4 per stage
#define RED_STRIDE_ 65              // 49 logits + 8 qx + 8 qy; 65%32==1 -> conflict-free
#define SMEM_TILES_F4_ (NGR_ * 2 * TILE_F4_)
#define SMEM_BYTES_ (SMEM_TILES_F4_ * 16 + 128 * RED_STRIDE_ * 4 + 112 * 4)

// cp.async a tile stage (zero-fill halo via src-size=0)
__device__ __forceinline__ void cp_stage(float4* __restrict__ dst,
                                         const float* __restrict__ base,
                                         int y0, int x0, int pid)
{
#pragma unroll
    for (int it = 0; it < 10; it++) {
        int i = pid + it * 128;
        if (i < TILE_F4_) {
            int c4  = i / PLANE_;
            int rem = i - c4 * PLANE_;
            int yy  = rem / KW_;
            int xx  = rem - yy * KW_;
            int gy = y0 - PAD_ + yy, gx = x0 - PAD_ + xx;
            bool inb = ((unsigned)gy < H_) && ((unsigned)gx < W_);
            const float* src = base + ((size_t)(inb ? gy : 0) * W_ + (inb ? gx : 0)) * CC_ + c4 * 4;
            unsigned daddr = (unsigned)__cvta_generic_to_shared(dst + i);
            int sz = inb ? 16 : 0;
            asm volatile("cp.async.cg.shared.global [%0], [%1], 16, %2;"
                         :: "r"(daddr), "l"(src), "r"(sz));
        }
    }
}
__device__ __forceinline__ void cp_commit() {
    asm volatile("cp.async.commit_group;" ::: "memory");
}
__device__ __forceinline__ void cp_wait_all() {
    asm volatile("cp.async.wait_all;" ::: "memory");
}
__device__ __forceinline__ void group_bar(int g) {
    asm volatile("bar.sync %0, %1;" :: "r"(1 + g), "r"(128) : "memory");
}

__global__ void __launch_bounds__(512, 1) attn_kernel(
    const float* __restrict__ relx, const float* __restrict__ rely,
    float* __restrict__ out)
{
    extern __shared__ float4 sm4[];
    float* red  = (float*)(sm4 + SMEM_TILES_F4_);
    float* srel = red + 128 * RED_STRIDE_;

    const int t   = threadIdx.x;
    const int g   = t >> 7;          // warp-group 0..3, owns chunks {2g, 2g+1}
    const int pid = t & 127;         // pixel id within tile
    const int tx  = pid & 15, ty = pid >> 4;
    const int b   = blockIdx.z;
    const int x0  = blockIdx.x * TW_, y0 = blockIdx.y * TH_;
    const int px  = x0 + tx, py = y0 + ty;

    if (t < 112) srel[t] = (t < 56) ? relx[t] : rely[t - 56];

    float4* tile = sm4 + g * (2 * TILE_F4_);
    const float* kb = g_qkv + MAT_STRIDE_;
    const float* vb = g_qkv + 2 * MAT_STRIDE_;

    // ---- prefetch both K chunk tiles for this group ----
    cp_stage(tile,            kb + (size_t)(b * NC_ + 2 * g    ) * CHUNK_STRIDE_, y0, x0, pid);
    cp_stage(tile + TILE_F4_, kb + (size_t)(b * NC_ + 2 * g + 1) * CHUNK_STRIDE_, y0, x0, pid);
    cp_commit();
    cp_wait_all();
    group_bar(g);

    float logit[49];
#pragma unroll
    for (int i = 0; i < 49; i++) logit[i] = 0.f;
    float qxs[8], qys[8];
#pragma unroll
    for (int i = 0; i < 8; i++) { qxs[i] = 0.f; qys[i] = 0.f; }

    // ---- pass 1: partial logits over this group's 2 chunks ----
#pragma unroll 1
    for (int s = 0; s < 2; s++) {
        const float4* tp = tile + s * TILE_F4_;
        const float4* qp = (const float4*)(g_qkv +
            (size_t)(b * NC_ + 2 * g + s) * CHUNK_STRIDE_ +
            ((size_t)py * W_ + px) * CC_);
        float4 q0 = qp[0], q1 = qp[1], q2 = qp[2], q3 = qp[3];

        qxs[0] += q0.x; qxs[1] += q0.y; qxs[2] += q0.z; qxs[3] += q0.w;
        qxs[4] += q1.x; qxs[5] += q1.y; qxs[6] += q1.z; qxs[7] += q1.w;
        qys[0] += q2.x; qys[1] += q2.y; qys[2] += q2.z; qys[3] += q2.w;
        qys[4] += q3.x; qys[5] += q3.y; qys[6] += q3.z; qys[7] += q3.w;

#pragma unroll
        for (int ki = 0; ki < KS_; ki++) {
#pragma unroll
            for (int kj = 0; kj < KS_; kj++) {
                int o = (ty + ki) * KW_ + tx + kj;
                float4 k0 = tp[0 * PLANE_ + o];
                float4 k1 = tp[1 * PLANE_ + o];
                float4 k2 = tp[2 * PLANE_ + o];
                float4 k3 = tp[3 * PLANE_ + o];
                float sacc = logit[ki * KS_ + kj];
                sacc = fmaf(q0.x, k0.x, sacc); sacc = fmaf(q0.y, k0.y, sacc);
                sacc = fmaf(q0.z, k0.z, sacc); sacc = fmaf(q0.w, k0.w, sacc);
                sacc = fmaf(q1.x, k1.x, sacc); sacc = fmaf(q1.y, k1.y, sacc);
                sacc = fmaf(q1.z, k1.z, sacc); sacc = fmaf(q1.w, k1.w, sacc);
                sacc = fmaf(q2.x, k2.x, sacc); sacc = fmaf(q2.y, k2.y, sacc);
                sacc = fmaf(q2.z, k2.z, sacc); sacc = fmaf(q2.w, k2.w, sacc);
                sacc = fmaf(q3.x, k3.x, sacc); sacc = fmaf(q3.y, k3.y, sacc);
                sacc = fmaf(q3.z, k3.z, sacc); sacc = fmaf(q3.w, k3.w, sacc);
                logit[ki * KS_ + kj] = sacc;
            }
        }
    }

    // group done reading K -> start V copies NOW; they complete under the reduction
    group_bar(g);
    cp_stage(tile,            vb + (size_t)(b * NC_ + 2 * g    ) * CHUNK_STRIDE_, y0, x0, pid);
    cp_stage(tile + TILE_F4_, vb + (size_t)(b * NC_ + 2 * g + 1) * CHUNK_STRIDE_, y0, x0, pid);
    cp_commit();

    // ---- cross-group reduction of (49 logits + 8 qx + 8 qy) ----
    float* rp = red + pid * RED_STRIDE_;
    __syncthreads();
    if (g == 0) {
#pragma unroll
        for (int j = 0; j < 49; j++) rp[j] = logit[j];
#pragma unroll
        for (int j = 0; j < 8; j++) { rp[49 + j] = qxs[j]; rp[57 + j] = qys[j]; }
    }
    __syncthreads();
    if (g == 1) {
#pragma unroll
        for (int j = 0; j < 49; j++) rp[j] += logit[j];
#pragma unroll
        for (int j = 0; j < 8; j++) { rp[49 + j] += qxs[j]; rp[57 + j] += qys[j]; }
    }
    __syncthreads();
    if (g == 2) {
#pragma unroll
        for (int j = 0; j < 49; j++) rp[j] += logit[j];
#pragma unroll
        for (int j = 0; j < 8; j++) { rp[49 + j] += qxs[j]; rp[57 + j] += qys[j]; }
    }
    __syncthreads();
    if (g == 3) {
#pragma unroll
        for (int j = 0; j < 49; j++) rp[j] += logit[j];
#pragma unroll
        for (int j = 0; j < 8; j++) { rp[49 + j] += qxs[j]; rp[57 + j] += qys[j]; }
    }
    __syncthreads();
#pragma unroll
    for (int j = 0; j < 49; j++) logit[j] = rp[j];
#pragma unroll
    for (int j = 0; j < 8; j++) { qxs[j] = rp[49 + j]; qys[j] = rp[57 + j]; }

    // ---- bias + softmax (thread-local, redundant across groups) ----
    float bxv[7], byv[7];
#pragma unroll
    for (int kj = 0; kj < 7; kj++) {
        float s = 0.f;
#pragma unroll
        for (int xi = 0; xi < 8; xi++) s = fmaf(qxs[xi], srel[xi * 7 + kj], s);
        bxv[kj] = s;
    }
#pragma unroll
    for (int ki = 0; ki < 7; ki++) {
        float s = 0.f;
#pragma unroll
        for (int yi = 0; yi < 8; yi++) s = fmaf(qys[yi], srel[56 + yi * 7 + ki], s);
        byv[ki] = s;
    }
    float m = -1e30f;
#pragma unroll
    for (int ki = 0; ki < 7; ki++)
#pragma unroll
        for (int kj = 0; kj < 7; kj++) {
            float l = logit[ki * 7 + kj] + bxv[kj] + byv[ki];
            logit[ki * 7 + kj] = l;
            m = fmaxf(m, l);
        }
    float ssum = 0.f;
#pragma unroll
    for (int i = 0; i < 49; i++) {
        float e = __expf(logit[i] - m);
        logit[i] = e;
        ssum += e;
    }
    float inv = 1.f / ssum;
#pragma unroll
    for (int i = 0; i < 49; i++) logit[i] *= inv;

    // ---- pass 2: V already in SMEM (copies overlapped with reduction) ----
    cp_wait_all();
    group_bar(g);

#pragma unroll 1
    for (int s = 0; s < 2; s++) {
        const float4* tp = tile + s * TILE_F4_;
        float4 o0 = make_float4(0.f, 0.f, 0.f, 0.f), o1 = o0, o2 = o0, o3 = o0;
#pragma unroll
        for (int ki = 0; ki < KS_; ki++) {
#pragma unroll
            for (int kj = 0; kj < KS_; kj++) {
                float a = logit[ki * KS_ + kj];
                int o = (ty + ki) * KW_ + tx + kj;
                float4 v0 = tp[0 * PLANE_ + o];
                float4 v1 = tp[1 * PLANE_ + o];
                float4 v2 = tp[2 * PLANE_ + o];
                float4 v3 = tp[3 * PLANE_ + o];
                o0.x = fmaf(a, v0.x, o0.x); o0.y = fmaf(a, v0.y, o0.y);
                o0.z = fmaf(a, v0.z, o0.z); o0.w = fmaf(a, v0.w, o0.w);
                o1.x = fmaf(a, v1.x, o1.x); o1.y = fmaf(a, v1.y, o1.y);
                o1.z = fmaf(a, v1.z, o1.z); o1.w = fmaf(a, v1.w, o1.w);
                o2.x = fmaf(a, v2.x, o2.x); o2.y = fmaf(a, v2.y, o2.y);
                o2.z = fmaf(a, v2.z, o2.z); o2.w = fmaf(a, v2.w, o2.w);
                o3.x = fmaf(a, v3.x, o3.x); o3.y = fmaf(a, v3.y, o3.y);
                o3.z = fmaf(a, v3.z, o3.z); o3.w = fmaf(a, v3.w, o3.w);
            }
        }
        int c = 2 * g + s;  // chunk -> output channels c*16 .. c*16+15
        size_t ob = ((size_t)(b * C_ + c * CC_) * H_ + py) * W_ + px;
        out[ob +  0 * HW_] = o0.x; out[ob +  1 * HW_] = o0.y;
        out[ob +  2 * HW_] = o0.z; out[ob +  3 * HW_] = o0.w;
        out[ob +  4 * HW_] = o1.x; out[ob +  5 * HW_] = o1.y;
        out[ob +  6 * HW_] = o1.z; out[ob +  7 * HW_] = o1.w;
        out[ob +  8 * HW_] = o2.x; out[ob +  9 * HW_] = o2.y;
        out[ob + 10 * HW_] = o2.z; out[ob + 11 * HW_] = o2.w;
        out[ob + 12 * HW_] = o3.x; out[ob + 13 * HW_] = o3.y;
        out[ob + 14 * HW_] = o3.z; out[ob + 15 * HW_] = o3.w;
    }
}

// ---------------- launch -----------------------------------------------------
extern "C" void kernel_launch(void* const* d_in, const int* in_sizes, int n_in,
                              void* d_out, int out_size)
{
    const float* x    = (const float*)d_in[0];
    const float* wq   = (const float*)d_in[1];
    const float* wk   = (const float*)d_in[2];
    const float* wv   = (const float*)d_in[3];
    const float* relx = (const float*)d_in[4];
    const float* rely = (const float*)d_in[5];
    float* out = (float*)d_out;

    // host-side attribute set (not a stream op; safe under graph capture)
    cudaFuncSetAttribute(attn_kernel,
                         cudaFuncAttributeMaxDynamicSharedMemorySize, SMEM_BYTES_);

    proj_kernel<<<dim3(B_ * H_, 3), 256>>>(x, wq, wk, wv);
    attn_kernel<<<dim3(W_ / TW_, H_ / TH_, B_), 512, SMEM_BYTES_>>>(relx, rely, out);
}